// round 5
// baseline (speedup 1.0000x reference)
#include <cuda_runtime.h>
#include <math.h>

// Problem constants (fixed by the reference)
#define HEAD_SIZE  128
#define HALF_ROT   64
#define NUM_TOKENS 8192
#define NUM_HEADS  32
#define ROW        6144          // (32 + 2*8) * 128
#define V_OFF      5120          // (32+8)*128 ; V slice = 1024 floats = 256 float4
#define EPS        1e-6f
#define GRID       592           // 148 SMs * 4 resident blocks

__global__ __launch_bounds__(256, 4)
void rope_qknorm_kernel(const float* __restrict__ qkv,
                        const float* __restrict__ qw,
                        const float* __restrict__ kw,
                        const int*   __restrict__ pos,
                        float*       __restrict__ out)
{
    // double-buffered per-token cos/sin tables: one barrier per token
    __shared__ float s_cos[2][HALF_ROT];
    __shared__ float s_sin[2][HALF_ROT];

    const int tid  = threadIdx.x;
    const int lane = tid & 31;
    const int warp = tid >> 5;

    // inv_freq[d] = 10000^(-d/64): double exp ONCE per block (correctly
    // rounded fp32; c = ln(10000)/64 = 0.14391156831212787)
    float invf = 0.0f;
    if (tid < HALF_ROT) {
        const double c = 0.14391156831212787;
        invf = (float)exp(-c * (double)tid);
    }

    // loop-invariant per-lane values
    const float4 wq = ((const float4*)qw)[lane];
    const float4 wk = ((const float4*)kw)[lane];
    const int   dlo = 4 * (lane & 15);               // rotary dim base 0..60
    const float sgn = (lane < 16) ? -1.0f : 1.0f;    // x1*c - x2*s | x2*c + x1*s

    int buf = 0;
    for (int t = blockIdx.x; t < NUM_TOKENS; t += GRID, buf ^= 1) {
        const float* row  = qkv + (size_t)t * ROW;
        float*       orow = out + (size_t)t * ROW;

        // cos/sin table for this token (threads 0..63)
        if (tid < HALF_ROT) {
            float ang = (float)pos[t] * invf;        // fp32 product = ref rounding
            float s, c;
            sincosf(ang, &s, &c);
            s_cos[buf][tid] = c;
            s_sin[buf][tid] = s;
        }

        // V passthrough: exactly 1024 floats = 256 float4 (streaming)
        {
            float4 v = __ldcs((const float4*)(row + V_OFF) + tid);
            __stcs((float4*)(orow + V_OFF) + tid, v);
        }

        // batch all 5 head loads (independent of the table)
        float4 y[5];
        #pragma unroll
        for (int i = 0; i < 5; i++)
            y[i] = __ldcs((const float4*)(row + (warp * 5 + i) * HEAD_SIZE) + lane);

        // rmsnorm in registers (no cos/sin dependency)
        #pragma unroll
        for (int i = 0; i < 5; i++) {
            const int h = warp * 5 + i;              // 0..39
            float ss = y[i].x * y[i].x + y[i].y * y[i].y
                     + y[i].z * y[i].z + y[i].w * y[i].w;
            #pragma unroll
            for (int o = 16; o; o >>= 1)
                ss += __shfl_xor_sync(0xffffffffu, ss, o);

            const float inv = rsqrtf(ss * (1.0f / 128.0f) + EPS);
            const float4 w  = (h < NUM_HEADS) ? wq : wk;
            y[i].x *= inv * w.x;
            y[i].y *= inv * w.y;
            y[i].z *= inv * w.z;
            y[i].w *= inv * w.w;
        }

        __syncthreads();   // table[buf] ready; also drains prior reads of buf

        const float4 cs = *(const float4*)(&s_cos[buf][dlo]);
        const float4 sn = *(const float4*)(&s_sin[buf][dlo]);

        // rope + streaming store
        #pragma unroll
        for (int i = 0; i < 5; i++) {
            const int h = warp * 5 + i;

            // partner half: dim d <-> d+64 lives exactly 16 lanes away
            float4 pr;
            pr.x = __shfl_xor_sync(0xffffffffu, y[i].x, 16);
            pr.y = __shfl_xor_sync(0xffffffffu, y[i].y, 16);
            pr.z = __shfl_xor_sync(0xffffffffu, y[i].z, 16);
            pr.w = __shfl_xor_sync(0xffffffffu, y[i].w, 16);

            float4 r;
            r.x = fmaf(sgn * pr.x, sn.x, y[i].x * cs.x);
            r.y = fmaf(sgn * pr.y, sn.y, y[i].y * cs.y);
            r.z = fmaf(sgn * pr.z, sn.z, y[i].z * cs.z);
            r.w = fmaf(sgn * pr.w, sn.w, y[i].w * cs.w);

            __stcs((float4*)(orow + h * HEAD_SIZE) + lane, r);
        }
    }
}

extern "C" void kernel_launch(void* const* d_in, const int* in_sizes, int n_in,
                              void* d_out, int out_size) {
    const float* qkv = (const float*)d_in[0];
    const float* qw  = (const float*)d_in[1];
    const float* kw  = (const float*)d_in[2];
    const int*   pos = (const int*)d_in[3];
    float* out = (float*)d_out;

    rope_qknorm_kernel<<<GRID, 256>>>(qkv, qw, kw, pos, out);
}

// round 6
// speedup vs baseline: 1.0644x; 1.0644x over previous
#include <cuda_runtime.h>
#include <math.h>

// Problem constants (fixed by the reference)
#define HEAD_SIZE  128
#define HALF_ROT   64
#define NUM_TOKENS 8192
#define NUM_HEADS  32
#define ROW        6144          // (32 + 2*8) * 128
#define V_OFF      5120          // (32+8)*128 ; V slice = 1024 floats = 256 float4
#define EPS        1e-6f

__global__ __launch_bounds__(256, 3)
void rope_qknorm_kernel(const float* __restrict__ qkv,
                        const float* __restrict__ qw,
                        const float* __restrict__ kw,
                        const int*   __restrict__ pos,
                        float*       __restrict__ out)
{
    // two per-token cos/sin tables (tokens 2b and 2b+1)
    __shared__ float s_cos[2][HALF_ROT];
    __shared__ float s_sin[2][HALF_ROT];

    const int tid  = threadIdx.x;
    const int lane = tid & 31;
    const int warp = tid >> 5;

    const int t0 = 2 * blockIdx.x;           // tokens t0, t0+1
    const float* row0  = qkv + (size_t)t0 * ROW;
    float*       orow0 = out + (size_t)t0 * ROW;

    // --- pos loads for both tokens, issued first (gate the trig chain) ---
    int p = 0;
    if (tid < 128) p = pos[t0 + (tid >> 6)];  // threads 0-63: t0, 64-127: t0+1

    // --- V passthrough for both tokens: 512 float4 / 256 threads ---
    {
        float4 v0 = __ldcs((const float4*)(row0 + V_OFF) + tid);
        float4 v1 = __ldcs((const float4*)(row0 + ROW + V_OFF) + tid);
        __stcs((float4*)(orow0 + V_OFF) + tid, v0);
        __stcs((float4*)(orow0 + ROW + V_OFF) + tid, v1);
    }

    // --- batch all 10 head loads (5 per token per warp) before the barrier ---
    float4 y0[5], y1[5];
    #pragma unroll
    for (int i = 0; i < 5; i++) {
        const int off = (warp * 5 + i) * HEAD_SIZE;
        y0[i] = __ldcs((const float4*)(row0 + off) + lane);
        y1[i] = __ldcs((const float4*)(row0 + ROW + off) + lane);
    }

    const float4 wq = ((const float4*)qw)[lane];
    const float4 wk = ((const float4*)kw)[lane];

    // --- cos/sin tables: threads 0-63 -> token0, 64-127 -> token1 ---
    // inv_freq[d] = 10000^(-d/64); double exp for correctly rounded fp32
    // (c = ln(10000)/64 = 0.14391156831212787). Overlaps in-flight LDGs.
    if (tid < 128) {
        const int d = tid & 63;
        const double c = 0.14391156831212787;
        const float invf = (float)exp(-c * (double)d);
        float ang = (float)p * invf;          // fp32 product = reference rounding
        float s, cc;
        sincosf(ang, &s, &cc);
        s_cos[tid >> 6][d] = cc;
        s_sin[tid >> 6][d] = s;
    }

    // --- rmsnorm both tokens in registers (no cos/sin dependency) ---
    #pragma unroll
    for (int i = 0; i < 5; i++) {
        const int h = warp * 5 + i;           // 0..39
        const float4 w = (h < NUM_HEADS) ? wq : wk;

        float ss0 = y0[i].x * y0[i].x + y0[i].y * y0[i].y
                  + y0[i].z * y0[i].z + y0[i].w * y0[i].w;
        float ss1 = y1[i].x * y1[i].x + y1[i].y * y1[i].y
                  + y1[i].z * y1[i].z + y1[i].w * y1[i].w;
        #pragma unroll
        for (int o = 16; o; o >>= 1) {
            ss0 += __shfl_xor_sync(0xffffffffu, ss0, o);
            ss1 += __shfl_xor_sync(0xffffffffu, ss1, o);
        }
        const float inv0 = rsqrtf(ss0 * (1.0f / 128.0f) + EPS);
        const float inv1 = rsqrtf(ss1 * (1.0f / 128.0f) + EPS);

        y0[i].x *= inv0 * w.x;  y0[i].y *= inv0 * w.y;
        y0[i].z *= inv0 * w.z;  y0[i].w *= inv0 * w.w;
        y1[i].x *= inv1 * w.x;  y1[i].y *= inv1 * w.y;
        y1[i].z *= inv1 * w.z;  y1[i].w *= inv1 * w.w;
    }

    __syncthreads();

    // --- per-lane rope invariants ---
    const int   dlo = 4 * (lane & 15);        // rotary dim base 0..60
    const float sgn = (lane < 16) ? -1.0f : 1.0f;

    // --- rope + streaming store, token 0 then token 1 ---
    #pragma unroll
    for (int tk = 0; tk < 2; tk++) {
        const float4 cs = *(const float4*)(&s_cos[tk][dlo]);
        const float4 sn = *(const float4*)(&s_sin[tk][dlo]);
        float*       od = orow0 + (size_t)tk * ROW;
        float4*      yy = tk ? y1 : y0;

        #pragma unroll
        for (int i = 0; i < 5; i++) {
            const int h = warp * 5 + i;

            // partner half: dim d <-> d+64 lives exactly 16 lanes away
            float4 pr;
            pr.x = __shfl_xor_sync(0xffffffffu, yy[i].x, 16);
            pr.y = __shfl_xor_sync(0xffffffffu, yy[i].y, 16);
            pr.z = __shfl_xor_sync(0xffffffffu, yy[i].z, 16);
            pr.w = __shfl_xor_sync(0xffffffffu, yy[i].w, 16);

            float4 r;
            r.x = fmaf(sgn * pr.x, sn.x, yy[i].x * cs.x);
            r.y = fmaf(sgn * pr.y, sn.y, yy[i].y * cs.y);
            r.z = fmaf(sgn * pr.z, sn.z, yy[i].z * cs.z);
            r.w = fmaf(sgn * pr.w, sn.w, yy[i].w * cs.w);

            __stcs((float4*)(od + h * HEAD_SIZE) + lane, r);
        }
    }
}

extern "C" void kernel_launch(void* const* d_in, const int* in_sizes, int n_in,
                              void* d_out, int out_size) {
    const float* qkv = (const float*)d_in[0];
    const float* qw  = (const float*)d_in[1];
    const float* kw  = (const float*)d_in[2];
    const int*   pos = (const int*)d_in[3];
    float* out = (float*)d_out;

    rope_qknorm_kernel<<<NUM_TOKENS / 2, 256>>>(qkv, qw, kw, pos, out);
}